// round 9
// baseline (speedup 1.0000x reference)
#include <cuda_runtime.h>
#include <cuda_fp16.h>
#include <cuda.h>

// DSSIM — fused separable-Gaussian SSIM + mean.
// Round 9: round-8 main (early TMA) + fused last-block reduction
// (threadfence ticket; fixed-order fp64 sum => deterministic).

#define IMH 512
#define IMW 512
#define TW 32
#define TH 64
#define SROWS 74            // TH + 10
#define STP 48              // TMA tile pitch in floats (192B rows)
#define INP 50              // fallback sIn pitch in float2 units
#define HP 33               // sH pitch in 8B units
#define GX 16
#define GY 8
#define NBLK (GX*GY*96)     // 12288
#define C1F 1.0e-4f
#define C2F 9.0e-4f
#define TMA_BYTES (2 * SROWS * STP * 4)   // 28416

typedef unsigned long long u64;

static __device__ __forceinline__ u64 pk2(float lo, float hi) {
    u64 r; asm("mov.b64 %0, {%1,%2};" : "=l"(r) : "f"(lo), "f"(hi)); return r;
}
static __device__ __forceinline__ void up2(u64 v, float& lo, float& hi) {
    asm("mov.b64 {%0,%1}, %2;" : "=f"(lo), "=f"(hi) : "l"(v));
}
static __device__ __forceinline__ u64 fma2(u64 a, u64 b, u64 c) {
    u64 d; asm("fma.rn.f32x2 %0, %1, %2, %3;" : "=l"(d) : "l"(a), "l"(b), "l"(c)); return d;
}
static __device__ __forceinline__ u64 add2(u64 a, u64 b) {
    u64 d; asm("add.rn.f32x2 %0, %1, %2;" : "=l"(d) : "l"(a), "l"(b)); return d;
}
static __device__ __forceinline__ unsigned smem32(const void* p) {
    unsigned a; asm("{ .reg .u64 t; cvta.to.shared.u64 t, %1; cvt.u32.u64 %0, t; }" : "=r"(a) : "l"(p));
    return a;
}

struct __align__(8) H2x2 { __half2 a, b; };   // (mu1', mu2'), (S', xy')

__device__ float    g_part[NBLK];
__device__ unsigned g_ctr;            // ticket counter; self-resets each run

// Accumulate shifted pixel pair (a', b') at tap kk into 8 streamed outputs.
#define ACCS(kk, va, vb) do {                                           \
    const float _s  = fmaf((va), (va), (vb) * (vb));                    \
    const float _xy = (va) * (vb);                                      \
    const u64 _A = pk2((va), (vb));                                     \
    const u64 _B = pk2(_s, _xy);                                        \
    _Pragma("unroll")                                                   \
    for (int j = 0; j < 8; ++j) {                                       \
        const int t = (kk) - j;                                         \
        if (t >= 0 && t <= 10) {                                        \
            const int wi = (t < 6) ? t : 10 - t;                        \
            aA[j] = fma2(ww[wi], _A, aA[j]);                            \
            aB[j] = fma2(ww[wi], _B, aB[j]);                            \
        }                                                               \
    }                                                                   \
} while (0)

// V-pass + SSIM epilogue + block partial + fused last-block finalization.
#define V_PASS_AND_REDUCE(OUTP)                                              \
    __half2 wh[6];                                                           \
    _Pragma("unroll")                                                        \
    for (int i = 0; i < 6; ++i) wh[i] = __float2half2_rn(sW[i]);             \
    const int x  = tid & 31;                                                 \
    const int ys = (tid >> 5) << 3;                                          \
    __half2 vA[8], vB[8];                                                    \
    const __half2 hz = __float2half2_rn(0.f);                                \
    _Pragma("unroll")                                                        \
    for (int j = 0; j < 8; ++j) { vA[j] = hz; vB[j] = hz; }                  \
    _Pragma("unroll")                                                        \
    for (int k = 0; k < 18; ++k) {                                           \
        const H2x2 h = sH[(ys + k) * HP + x];                                \
        _Pragma("unroll")                                                    \
        for (int j = 0; j < 8; ++j) {                                        \
            const int t = k - j;                                             \
            if (t >= 0 && t <= 10) {                                         \
                const int wi = (t < 6) ? t : 10 - t;                         \
                vA[j] = __hfma2(wh[wi], h.a, vA[j]);                         \
                vB[j] = __hfma2(wh[wi], h.b, vB[j]);                         \
            }                                                                \
        }                                                                    \
    }                                                                        \
    float local = 0.f;                                                       \
    _Pragma("unroll")                                                        \
    for (int j = 0; j < 8; ++j) {                                            \
        const float2 m  = __half22float2(vA[j]);  /* mu1', mu2' */           \
        const float2 sx = __half22float2(vB[j]);  /* S', bxy' */             \
        const float t2 = m.x + m.y;                                          \
        const float p  = m.x * m.y;                                          \
        const float q2 = fmaf(m.x, m.x, m.y * m.y);                          \
        const float mu12 = fmaf(0.5f, t2, p + 0.25f);                        \
        const float A2   = q2 + t2 + 0.5f;                                   \
        const float s12  = sx.y - p;                                         \
        const float sS   = sx.x - q2;                                        \
        const float num = fmaf(2.f, mu12, C1F) * fmaf(2.f, s12, C2F);        \
        const float den = (A2 + C1F) * (sS + C2F);                           \
        local += (1.f - __fdividef(num, den)) * 0.5f;                        \
    }                                                                        \
    _Pragma("unroll")                                                        \
    for (int o = 16; o; o >>= 1) local += __shfl_xor_sync(0xffffffffu, local, o); \
    if ((tid & 31) == 0) sWarp[tid >> 5] = local;                            \
    __syncthreads();                                                         \
    if (tid == 0) {                                                          \
        float bs = 0.f;                                                      \
        _Pragma("unroll")                                                    \
        for (int i = 0; i < 8; ++i) bs += sWarp[i];                          \
        g_part[((int)blockIdx.z * GY + (int)blockIdx.y) * GX + (int)blockIdx.x] = bs; \
        __threadfence();                                                     \
        const unsigned prev = atomicAdd(&g_ctr, 1u);                         \
        sLast = (prev == NBLK - 1) ? 1u : 0u;                                \
    }                                                                        \
    __syncthreads();                                                         \
    if (sLast) {                                                             \
        __threadfence();                                                     \
        double s = 0.0;                                                      \
        _Pragma("unroll")                                                    \
        for (int i = 0; i < NBLK / 256; ++i)   /* fixed order: deterministic */ \
            s += (double)g_part[tid + (i << 8)];                             \
        sd[tid] = s;                                                         \
        __syncthreads();                                                     \
        _Pragma("unroll")                                                    \
        for (int o = 128; o; o >>= 1) {                                      \
            if (tid < o) sd[tid] += sd[tid + o];                             \
            __syncthreads();                                                 \
        }                                                                    \
        if (tid == 0) {                                                      \
            (OUTP)[0] = (float)(sd[0] / (double)(32.0 * 3.0 * 512.0 * 512.0)); \
            g_ctr = 0u;   /* reset for next graph replay */                  \
            __threadfence();                                                 \
        }                                                                    \
    }

// ---------------------------------------------------------------------------
// TMA path
// ---------------------------------------------------------------------------
__global__ __launch_bounds__(256, 4) void dssim_tma(
    const __grid_constant__ CUtensorMap tm1,
    const __grid_constant__ CUtensorMap tm2,
    const float* __restrict__ kern,
    float* __restrict__ out)
{
    __shared__ alignas(128) float sT1[SROWS * STP];
    __shared__ alignas(128) float sT2[SROWS * STP];
    __shared__ alignas(16)  H2x2  sH[SROWS * HP];
    __shared__ alignas(8)   u64   mbar;
    __shared__ double sd[256];
    __shared__ float  sW[6];
    __shared__ float  sWarp[8];
    __shared__ unsigned sLast;

    const int tid = threadIdx.x;
    const int x0 = blockIdx.x * TW;
    const int y0 = blockIdx.y * TH;

    // tid0: init barrier, fence, and launch both TMA loads immediately.
    if (tid == 0) {
        const unsigned mb = smem32(&mbar);
        asm volatile("mbarrier.init.shared.b64 [%0], 1;" :: "r"(mb) : "memory");
        asm volatile("fence.proxy.async.shared::cta;" ::: "memory");
        asm volatile("mbarrier.arrive.expect_tx.shared.b64 _, [%0], %1;"
                     :: "r"(mb), "r"((unsigned)TMA_BYTES) : "memory");
        const int cx = x0 - 8, cy = y0 - 5, cz = blockIdx.z;
        asm volatile("cp.async.bulk.tensor.3d.shared::cta.global.tile.mbarrier::complete_tx::bytes "
                     "[%0], [%1, {%2, %3, %4}], [%5];"
                     :: "r"(smem32(sT1)), "l"(&tm1), "r"(cx), "r"(cy), "r"(cz), "r"(mb) : "memory");
        asm volatile("cp.async.bulk.tensor.3d.shared::cta.global.tile.mbarrier::complete_tx::bytes "
                     "[%0], [%1, {%2, %3, %4}], [%5];"
                     :: "r"(smem32(sT2)), "l"(&tm2), "r"(cx), "r"(cy), "r"(cz), "r"(mb) : "memory");
    }
    // Weight prep overlaps the TMA flight.
    if (tid < 6) {
        float s = 0.f;
        #pragma unroll
        for (int j = 0; j < 11; ++j) s += kern[tid * 11 + j];
        sW[tid] = s;
    }
    __syncthreads();   // orders mbarrier.init before other threads' try_wait

    u64 ww[6];
    #pragma unroll
    for (int i = 0; i < 6; ++i) { float w = sW[i]; ww[i] = pk2(w, w); }
    const u64 NEGH = pk2(-0.5f, -0.5f);

    // wait for TMA (acquire)
    {
        const unsigned mb = smem32(&mbar);
        unsigned done;
        asm volatile("{\n\t.reg .pred p;\n\t"
                     "mbarrier.try_wait.parity.acquire.cta.shared::cta.b64 p, [%1], 0;\n\t"
                     "selp.b32 %0, 1, 0, p;\n\t}"
                     : "=r"(done) : "r"(mb) : "memory");
        if (!done) {
            asm volatile("{\n\t.reg .pred P1;\n\t"
                         "W0_%=:\n\t"
                         "mbarrier.try_wait.parity.acquire.cta.shared::cta.b64 P1, [%0], 0, 0x989680;\n\t"
                         "@P1 bra.uni W1_%=;\n\t"
                         "bra.uni W0_%=;\n\t"
                         "W1_%=:\n\t}" :: "r"(mb) : "memory");
        }
    }

    // ---- H-pass: 296 tasks (74 rows x 4 groups-of-8), LDS.128 from both tiles ----
    for (int g = tid; g < SROWS * 4; g += 256) {
        const int r  = g >> 2;
        const int cx = (g & 3) << 3;
        u64 aA[8], aB[8];
        #pragma unroll
        for (int j = 0; j < 8; ++j) { aA[j] = 0ull; aB[j] = 0ull; }

        const float4* r1 = (const float4*)&sT1[r * STP];
        const float4* r2 = (const float4*)&sT2[r * STP];
        const int qb = cx >> 2;
        #pragma unroll
        for (int qi = 0; qi < 6; ++qi) {
            const float4 A4 = r1[qb + qi];
            const float4 B4 = r2[qb + qi];
            u64 pa, pb; float a0,a1,b0,b1,a2,a3,b2,b3;
            pa = add2(pk2(A4.x, A4.y), NEGH); up2(pa, a0, a1);
            pb = add2(pk2(B4.x, B4.y), NEGH); up2(pb, b0, b1);
            {
                const int k = 4 * qi - 3;
                if (k >= 0 && k <= 17) ACCS(k, a0, b0);
                if (k + 1 >= 0 && k + 1 <= 17) ACCS(k + 1, a1, b1);
            }
            pa = add2(pk2(A4.z, A4.w), NEGH); up2(pa, a2, a3);
            pb = add2(pk2(B4.z, B4.w), NEGH); up2(pb, b2, b3);
            {
                const int k = 4 * qi - 1;
                if (k >= 0 && k <= 17) ACCS(k, a2, b2);
                if (k + 1 <= 17) ACCS(k + 1, a3, b3);
            }
        }

        #pragma unroll
        for (int j = 0; j < 8; ++j) {
            float m1, m2, s, xy;
            up2(aA[j], m1, m2);
            up2(aB[j], s, xy);
            H2x2 h;
            h.a = __floats2half2_rn(m1, m2);
            h.b = __floats2half2_rn(s, xy);
            sH[r * HP + cx + j] = h;
        }
    }
    __syncthreads();

    V_PASS_AND_REDUCE(out)
}

// ---------------------------------------------------------------------------
// Fallback path (LDG staging), same math
// ---------------------------------------------------------------------------
__global__ __launch_bounds__(256, 4) void dssim_ldg(
    const float* __restrict__ im1,
    const float* __restrict__ im2,
    const float* __restrict__ kern,
    float* __restrict__ out)
{
    __shared__ float2 sIn[SROWS * INP];
    __shared__ H2x2   sH[SROWS * HP];
    __shared__ double sd[256];
    __shared__ float  sW[6];
    __shared__ float  sWarp[8];
    __shared__ unsigned sLast;

    const int tid = threadIdx.x;
    const int x0 = blockIdx.x * TW;
    const int y0 = blockIdx.y * TH;
    const size_t pbase = (size_t)blockIdx.z * (IMH * IMW);

    if (tid < 6) {
        float s = 0.f;
        #pragma unroll
        for (int j = 0; j < 11; ++j) s += kern[tid * 11 + j];
        sW[tid] = s;
    }

    for (int i = tid; i < SROWS * 12; i += 256) {
        const int r = i / 12;
        const int q = i - r * 12;
        const int gy = y0 + r - 5;
        const int gx = x0 + (q << 2) - 8;
        float4 a = make_float4(0.f, 0.f, 0.f, 0.f);
        float4 b = a;
        if ((unsigned)gy < IMH && gx >= 0 && gx <= IMW - 4) {
            const size_t o = pbase + (size_t)gy * IMW + gx;
            a = *(const float4*)(im1 + o);
            b = *(const float4*)(im2 + o);
        }
        float4* dst = (float4*)&sIn[r * INP + (q << 2)];
        dst[0] = make_float4(a.x - 0.5f, b.x - 0.5f, a.y - 0.5f, b.y - 0.5f);
        dst[1] = make_float4(a.z - 0.5f, b.z - 0.5f, a.w - 0.5f, b.w - 0.5f);
    }
    __syncthreads();

    u64 ww[6];
    #pragma unroll
    for (int i = 0; i < 6; ++i) { float w = sW[i]; ww[i] = pk2(w, w); }

    for (int g = tid; g < SROWS * 4; g += 256) {
        const int r  = g >> 2;
        const int cx = (g & 3) << 3;
        u64 aA[8], aB[8];
        #pragma unroll
        for (int j = 0; j < 8; ++j) { aA[j] = 0ull; aB[j] = 0ull; }

        const float4* rp4 = (const float4*)&sIn[r * INP];
        const int qb = (cx >> 1) + 1;
        #pragma unroll
        for (int q = 0; q < 10; ++q) {
            const float4 L = rp4[qb + q];
            if (q > 0) ACCS(2 * q - 1, L.x, L.y);
            if (q < 9) ACCS(2 * q,     L.z, L.w);
        }

        #pragma unroll
        for (int j = 0; j < 8; ++j) {
            float m1, m2, s, xy;
            up2(aA[j], m1, m2);
            up2(aB[j], s, xy);
            H2x2 h;
            h.a = __floats2half2_rn(m1, m2);
            h.b = __floats2half2_rn(s, xy);
            sH[r * HP + cx + j] = h;
        }
    }
    __syncthreads();

    V_PASS_AND_REDUCE(out)
}

// ---------------------------------------------------------------------------
// Host
// ---------------------------------------------------------------------------
typedef CUresult (*PFN_tmap_encode)(
    CUtensorMap*, CUtensorMapDataType, cuuint32_t, void*,
    const cuuint64_t*, const cuuint64_t*, const cuuint32_t*, const cuuint32_t*,
    CUtensorMapInterleave, CUtensorMapSwizzle, CUtensorMapL2promotion,
    CUtensorMapFloatOOBfill);

static bool build_tmap(PFN_tmap_encode enc, CUtensorMap* tm, const void* ptr)
{
    cuuint64_t dims[3]    = {IMW, IMH, 96};
    cuuint64_t strides[2] = {IMW * 4ull, (cuuint64_t)IMH * IMW * 4ull};
    cuuint32_t box[3]     = {STP, SROWS, 1};
    cuuint32_t es[3]      = {1, 1, 1};
    return enc(tm, CU_TENSOR_MAP_DATA_TYPE_FLOAT32, 3, (void*)ptr,
               dims, strides, box, es,
               CU_TENSOR_MAP_INTERLEAVE_NONE, CU_TENSOR_MAP_SWIZZLE_NONE,
               CU_TENSOR_MAP_L2_PROMOTION_L2_128B,
               CU_TENSOR_MAP_FLOAT_OOB_FILL_NONE) == CUDA_SUCCESS;
}

extern "C" void kernel_launch(void* const* d_in, const int* in_sizes, int n_in,
                              void* d_out, int out_size)
{
    const float* im1  = (const float*)d_in[0];
    const float* im2  = (const float*)d_in[1];
    const float* kern = (const float*)d_in[2];
    float* out = (float*)d_out;

    dim3 grid(GX, GY, 96);

    PFN_tmap_encode enc = nullptr;
    {
        void* fp = nullptr;
        cudaDriverEntryPointQueryResult st = cudaDriverEntryPointSymbolNotFound;
        if (cudaGetDriverEntryPoint("cuTensorMapEncodeTiled", &fp,
                                    cudaEnableDefault, &st) == cudaSuccess &&
            st == cudaDriverEntryPointSuccess)
            enc = (PFN_tmap_encode)fp;
    }

    CUtensorMap tm1, tm2;
    bool tma_ok = enc && build_tmap(enc, &tm1, im1) && build_tmap(enc, &tm2, im2);

    if (tma_ok)
        dssim_tma<<<grid, 256>>>(tm1, tm2, kern, out);
    else
        dssim_ldg<<<grid, 256>>>(im1, im2, kern, out);
}

// round 10
// speedup vs baseline: 1.0605x; 1.0605x over previous
#include <cuda_runtime.h>
#include <cuda_fp16.h>
#include <cuda.h>

// DSSIM — fused separable-Gaussian SSIM + mean.
// Round 10: proven-best combination — round-8 main (early TMA issue,
// standalone) + round-7 two-stage reduction tail.

#define IMH 512
#define IMW 512
#define TW 32
#define TH 64
#define SROWS 74            // TH + 10
#define STP 48              // TMA tile pitch in floats (192B rows)
#define INP 50              // fallback sIn pitch in float2 units
#define HP 33               // sH pitch in 8B units
#define GX 16
#define GY 8
#define NBLK (GX*GY*96)     // 12288
#define NRED1 48            // 48*256 = 12288
#define C1F 1.0e-4f
#define C2F 9.0e-4f
#define TMA_BYTES (2 * SROWS * STP * 4)   // 28416

typedef unsigned long long u64;

static __device__ __forceinline__ u64 pk2(float lo, float hi) {
    u64 r; asm("mov.b64 %0, {%1,%2};" : "=l"(r) : "f"(lo), "f"(hi)); return r;
}
static __device__ __forceinline__ void up2(u64 v, float& lo, float& hi) {
    asm("mov.b64 {%0,%1}, %2;" : "=f"(lo), "=f"(hi) : "l"(v));
}
static __device__ __forceinline__ u64 fma2(u64 a, u64 b, u64 c) {
    u64 d; asm("fma.rn.f32x2 %0, %1, %2, %3;" : "=l"(d) : "l"(a), "l"(b), "l"(c)); return d;
}
static __device__ __forceinline__ u64 add2(u64 a, u64 b) {
    u64 d; asm("add.rn.f32x2 %0, %1, %2;" : "=l"(d) : "l"(a), "l"(b)); return d;
}
static __device__ __forceinline__ unsigned smem32(const void* p) {
    unsigned a; asm("{ .reg .u64 t; cvta.to.shared.u64 t, %1; cvt.u32.u64 %0, t; }" : "=r"(a) : "l"(p));
    return a;
}

struct __align__(8) H2x2 { __half2 a, b; };   // (mu1', mu2'), (S', xy')

__device__ float  g_part[NBLK];
__device__ double g_part2[NRED1];

// Accumulate shifted pixel pair (a', b') at tap kk into 8 streamed outputs.
#define ACCS(kk, va, vb) do {                                           \
    const float _s  = fmaf((va), (va), (vb) * (vb));                    \
    const float _xy = (va) * (vb);                                      \
    const u64 _A = pk2((va), (vb));                                     \
    const u64 _B = pk2(_s, _xy);                                        \
    _Pragma("unroll")                                                   \
    for (int j = 0; j < 8; ++j) {                                       \
        const int t = (kk) - j;                                         \
        if (t >= 0 && t <= 10) {                                        \
            const int wi = (t < 6) ? t : 10 - t;                        \
            aA[j] = fma2(ww[wi], _A, aA[j]);                            \
            aB[j] = fma2(ww[wi], _B, aB[j]);                            \
        }                                                               \
    }                                                                   \
} while (0)

// V-pass + SSIM epilogue + block partial (shared by both kernels).
#define V_PASS_AND_REDUCE()                                                  \
    __half2 wh[6];                                                           \
    _Pragma("unroll")                                                        \
    for (int i = 0; i < 6; ++i) wh[i] = __float2half2_rn(sW[i]);             \
    const int x  = tid & 31;                                                 \
    const int ys = (tid >> 5) << 3;                                          \
    __half2 vA[8], vB[8];                                                    \
    const __half2 hz = __float2half2_rn(0.f);                                \
    _Pragma("unroll")                                                        \
    for (int j = 0; j < 8; ++j) { vA[j] = hz; vB[j] = hz; }                  \
    _Pragma("unroll")                                                        \
    for (int k = 0; k < 18; ++k) {                                           \
        const H2x2 h = sH[(ys + k) * HP + x];                                \
        _Pragma("unroll")                                                    \
        for (int j = 0; j < 8; ++j) {                                        \
            const int t = k - j;                                             \
            if (t >= 0 && t <= 10) {                                         \
                const int wi = (t < 6) ? t : 10 - t;                         \
                vA[j] = __hfma2(wh[wi], h.a, vA[j]);                         \
                vB[j] = __hfma2(wh[wi], h.b, vB[j]);                         \
            }                                                                \
        }                                                                    \
    }                                                                        \
    float local = 0.f;                                                       \
    _Pragma("unroll")                                                        \
    for (int j = 0; j < 8; ++j) {                                            \
        const float2 m  = __half22float2(vA[j]);  /* mu1', mu2' */           \
        const float2 sx = __half22float2(vB[j]);  /* S', bxy' */             \
        const float t2 = m.x + m.y;                                          \
        const float p  = m.x * m.y;                                          \
        const float q2 = fmaf(m.x, m.x, m.y * m.y);                          \
        const float mu12 = fmaf(0.5f, t2, p + 0.25f);                        \
        const float A2   = q2 + t2 + 0.5f;                                   \
        const float s12  = sx.y - p;                                         \
        const float sS   = sx.x - q2;                                        \
        const float num = fmaf(2.f, mu12, C1F) * fmaf(2.f, s12, C2F);        \
        const float den = (A2 + C1F) * (sS + C2F);                           \
        local += (1.f - __fdividef(num, den)) * 0.5f;                        \
    }                                                                        \
    _Pragma("unroll")                                                        \
    for (int o = 16; o; o >>= 1) local += __shfl_xor_sync(0xffffffffu, local, o); \
    if ((tid & 31) == 0) sWarp[tid >> 5] = local;                            \
    __syncthreads();                                                         \
    if (tid == 0) {                                                          \
        float bs = 0.f;                                                      \
        _Pragma("unroll")                                                    \
        for (int i = 0; i < 8; ++i) bs += sWarp[i];                          \
        g_part[((int)blockIdx.z * GY + (int)blockIdx.y) * GX + (int)blockIdx.x] = bs; \
    }

// ---------------------------------------------------------------------------
// TMA path
// ---------------------------------------------------------------------------
__global__ __launch_bounds__(256, 4) void dssim_tma(
    const __grid_constant__ CUtensorMap tm1,
    const __grid_constant__ CUtensorMap tm2,
    const float* __restrict__ kern)
{
    __shared__ alignas(128) float sT1[SROWS * STP];
    __shared__ alignas(128) float sT2[SROWS * STP];
    __shared__ alignas(16)  H2x2  sH[SROWS * HP];
    __shared__ alignas(8)   u64   mbar;
    __shared__ float sW[6];
    __shared__ float sWarp[8];

    const int tid = threadIdx.x;
    const int x0 = blockIdx.x * TW;
    const int y0 = blockIdx.y * TH;

    // tid0: init barrier, fence, and launch both TMA loads immediately.
    if (tid == 0) {
        const unsigned mb = smem32(&mbar);
        asm volatile("mbarrier.init.shared.b64 [%0], 1;" :: "r"(mb) : "memory");
        asm volatile("fence.proxy.async.shared::cta;" ::: "memory");
        asm volatile("mbarrier.arrive.expect_tx.shared.b64 _, [%0], %1;"
                     :: "r"(mb), "r"((unsigned)TMA_BYTES) : "memory");
        const int cx = x0 - 8, cy = y0 - 5, cz = blockIdx.z;
        asm volatile("cp.async.bulk.tensor.3d.shared::cta.global.tile.mbarrier::complete_tx::bytes "
                     "[%0], [%1, {%2, %3, %4}], [%5];"
                     :: "r"(smem32(sT1)), "l"(&tm1), "r"(cx), "r"(cy), "r"(cz), "r"(mb) : "memory");
        asm volatile("cp.async.bulk.tensor.3d.shared::cta.global.tile.mbarrier::complete_tx::bytes "
                     "[%0], [%1, {%2, %3, %4}], [%5];"
                     :: "r"(smem32(sT2)), "l"(&tm2), "r"(cx), "r"(cy), "r"(cz), "r"(mb) : "memory");
    }
    // Weight prep overlaps the TMA flight.
    if (tid < 6) {
        float s = 0.f;
        #pragma unroll
        for (int j = 0; j < 11; ++j) s += kern[tid * 11 + j];
        sW[tid] = s;
    }
    __syncthreads();   // orders mbarrier.init before other threads' try_wait

    u64 ww[6];
    #pragma unroll
    for (int i = 0; i < 6; ++i) { float w = sW[i]; ww[i] = pk2(w, w); }
    const u64 NEGH = pk2(-0.5f, -0.5f);

    // wait for TMA (acquire)
    {
        const unsigned mb = smem32(&mbar);
        unsigned done;
        asm volatile("{\n\t.reg .pred p;\n\t"
                     "mbarrier.try_wait.parity.acquire.cta.shared::cta.b64 p, [%1], 0;\n\t"
                     "selp.b32 %0, 1, 0, p;\n\t}"
                     : "=r"(done) : "r"(mb) : "memory");
        if (!done) {
            asm volatile("{\n\t.reg .pred P1;\n\t"
                         "W0_%=:\n\t"
                         "mbarrier.try_wait.parity.acquire.cta.shared::cta.b64 P1, [%0], 0, 0x989680;\n\t"
                         "@P1 bra.uni W1_%=;\n\t"
                         "bra.uni W0_%=;\n\t"
                         "W1_%=:\n\t}" :: "r"(mb) : "memory");
        }
    }

    // ---- H-pass: 296 tasks (74 rows x 4 groups-of-8), LDS.128 from both tiles ----
    for (int g = tid; g < SROWS * 4; g += 256) {
        const int r  = g >> 2;
        const int cx = (g & 3) << 3;
        u64 aA[8], aB[8];
        #pragma unroll
        for (int j = 0; j < 8; ++j) { aA[j] = 0ull; aB[j] = 0ull; }

        const float4* r1 = (const float4*)&sT1[r * STP];
        const float4* r2 = (const float4*)&sT2[r * STP];
        const int qb = cx >> 2;
        #pragma unroll
        for (int qi = 0; qi < 6; ++qi) {
            const float4 A4 = r1[qb + qi];
            const float4 B4 = r2[qb + qi];
            u64 pa, pb; float a0,a1,b0,b1,a2,a3,b2,b3;
            pa = add2(pk2(A4.x, A4.y), NEGH); up2(pa, a0, a1);
            pb = add2(pk2(B4.x, B4.y), NEGH); up2(pb, b0, b1);
            {
                const int k = 4 * qi - 3;
                if (k >= 0 && k <= 17) ACCS(k, a0, b0);
                if (k + 1 >= 0 && k + 1 <= 17) ACCS(k + 1, a1, b1);
            }
            pa = add2(pk2(A4.z, A4.w), NEGH); up2(pa, a2, a3);
            pb = add2(pk2(B4.z, B4.w), NEGH); up2(pb, b2, b3);
            {
                const int k = 4 * qi - 1;
                if (k >= 0 && k <= 17) ACCS(k, a2, b2);
                if (k + 1 <= 17) ACCS(k + 1, a3, b3);
            }
        }

        #pragma unroll
        for (int j = 0; j < 8; ++j) {
            float m1, m2, s, xy;
            up2(aA[j], m1, m2);
            up2(aB[j], s, xy);
            H2x2 h;
            h.a = __floats2half2_rn(m1, m2);
            h.b = __floats2half2_rn(s, xy);
            sH[r * HP + cx + j] = h;
        }
    }
    __syncthreads();

    V_PASS_AND_REDUCE()
}

// ---------------------------------------------------------------------------
// Fallback path (LDG staging), same math
// ---------------------------------------------------------------------------
__global__ __launch_bounds__(256, 4) void dssim_ldg(
    const float* __restrict__ im1,
    const float* __restrict__ im2,
    const float* __restrict__ kern)
{
    __shared__ float2 sIn[SROWS * INP];
    __shared__ H2x2   sH[SROWS * HP];
    __shared__ float  sW[6];
    __shared__ float  sWarp[8];

    const int tid = threadIdx.x;
    const int x0 = blockIdx.x * TW;
    const int y0 = blockIdx.y * TH;
    const size_t pbase = (size_t)blockIdx.z * (IMH * IMW);

    if (tid < 6) {
        float s = 0.f;
        #pragma unroll
        for (int j = 0; j < 11; ++j) s += kern[tid * 11 + j];
        sW[tid] = s;
    }

    for (int i = tid; i < SROWS * 12; i += 256) {
        const int r = i / 12;
        const int q = i - r * 12;
        const int gy = y0 + r - 5;
        const int gx = x0 + (q << 2) - 8;
        float4 a = make_float4(0.f, 0.f, 0.f, 0.f);
        float4 b = a;
        if ((unsigned)gy < IMH && gx >= 0 && gx <= IMW - 4) {
            const size_t o = pbase + (size_t)gy * IMW + gx;
            a = *(const float4*)(im1 + o);
            b = *(const float4*)(im2 + o);
        }
        float4* dst = (float4*)&sIn[r * INP + (q << 2)];
        dst[0] = make_float4(a.x - 0.5f, b.x - 0.5f, a.y - 0.5f, b.y - 0.5f);
        dst[1] = make_float4(a.z - 0.5f, b.z - 0.5f, a.w - 0.5f, b.w - 0.5f);
    }
    __syncthreads();

    u64 ww[6];
    #pragma unroll
    for (int i = 0; i < 6; ++i) { float w = sW[i]; ww[i] = pk2(w, w); }

    for (int g = tid; g < SROWS * 4; g += 256) {
        const int r  = g >> 2;
        const int cx = (g & 3) << 3;
        u64 aA[8], aB[8];
        #pragma unroll
        for (int j = 0; j < 8; ++j) { aA[j] = 0ull; aB[j] = 0ull; }

        const float4* rp4 = (const float4*)&sIn[r * INP];
        const int qb = (cx >> 1) + 1;
        #pragma unroll
        for (int q = 0; q < 10; ++q) {
            const float4 L = rp4[qb + q];
            if (q > 0) ACCS(2 * q - 1, L.x, L.y);
            if (q < 9) ACCS(2 * q,     L.z, L.w);
        }

        #pragma unroll
        for (int j = 0; j < 8; ++j) {
            float m1, m2, s, xy;
            up2(aA[j], m1, m2);
            up2(aB[j], s, xy);
            H2x2 h;
            h.a = __floats2half2_rn(m1, m2);
            h.b = __floats2half2_rn(s, xy);
            sH[r * HP + cx + j] = h;
        }
    }
    __syncthreads();

    V_PASS_AND_REDUCE()
}

// ---------------------------------------------------------------------------
// Two-stage deterministic reduction (round-7 proven tail, 5.8 us)
// ---------------------------------------------------------------------------
__global__ __launch_bounds__(256) void dssim_reduce1()
{
    __shared__ double sd[256];
    const int t = threadIdx.x;
    sd[t] = (double)g_part[blockIdx.x * 256 + t];
    __syncthreads();
    #pragma unroll
    for (int o = 128; o; o >>= 1) {
        if (t < o) sd[t] += sd[t + o];
        __syncthreads();
    }
    if (t == 0) g_part2[blockIdx.x] = sd[0];
}

__global__ __launch_bounds__(64) void dssim_reduce2(float* __restrict__ out)
{
    __shared__ double sd[64];
    const int t = threadIdx.x;
    sd[t] = (t < NRED1) ? g_part2[t] : 0.0;
    __syncthreads();
    #pragma unroll
    for (int o = 32; o; o >>= 1) {
        if (t < o) sd[t] += sd[t + o];
        __syncthreads();
    }
    if (t == 0) out[0] = (float)(sd[0] / (double)(32.0 * 3.0 * 512.0 * 512.0));
}

// ---------------------------------------------------------------------------
// Host
// ---------------------------------------------------------------------------
typedef CUresult (*PFN_tmap_encode)(
    CUtensorMap*, CUtensorMapDataType, cuuint32_t, void*,
    const cuuint64_t*, const cuuint64_t*, const cuuint32_t*, const cuuint32_t*,
    CUtensorMapInterleave, CUtensorMapSwizzle, CUtensorMapL2promotion,
    CUtensorMapFloatOOBfill);

static bool build_tmap(PFN_tmap_encode enc, CUtensorMap* tm, const void* ptr)
{
    cuuint64_t dims[3]    = {IMW, IMH, 96};
    cuuint64_t strides[2] = {IMW * 4ull, (cuuint64_t)IMH * IMW * 4ull};
    cuuint32_t box[3]     = {STP, SROWS, 1};
    cuuint32_t es[3]      = {1, 1, 1};
    return enc(tm, CU_TENSOR_MAP_DATA_TYPE_FLOAT32, 3, (void*)ptr,
               dims, strides, box, es,
               CU_TENSOR_MAP_INTERLEAVE_NONE, CU_TENSOR_MAP_SWIZZLE_NONE,
               CU_TENSOR_MAP_L2_PROMOTION_L2_128B,
               CU_TENSOR_MAP_FLOAT_OOB_FILL_NONE) == CUDA_SUCCESS;
}

extern "C" void kernel_launch(void* const* d_in, const int* in_sizes, int n_in,
                              void* d_out, int out_size)
{
    const float* im1  = (const float*)d_in[0];
    const float* im2  = (const float*)d_in[1];
    const float* kern = (const float*)d_in[2];
    float* out = (float*)d_out;

    dim3 grid(GX, GY, 96);

    PFN_tmap_encode enc = nullptr;
    {
        void* fp = nullptr;
        cudaDriverEntryPointQueryResult st = cudaDriverEntryPointSymbolNotFound;
        if (cudaGetDriverEntryPoint("cuTensorMapEncodeTiled", &fp,
                                    cudaEnableDefault, &st) == cudaSuccess &&
            st == cudaDriverEntryPointSuccess)
            enc = (PFN_tmap_encode)fp;
    }

    CUtensorMap tm1, tm2;
    bool tma_ok = enc && build_tmap(enc, &tm1, im1) && build_tmap(enc, &tm2, im2);

    if (tma_ok)
        dssim_tma<<<grid, 256>>>(tm1, tm2, kern);
    else
        dssim_ldg<<<grid, 256>>>(im1, im2, kern);

    dssim_reduce1<<<NRED1, 256>>>();
    dssim_reduce2<<<1, 64>>>(out);
}

// round 11
// speedup vs baseline: 1.0633x; 1.0027x over previous
#include <cuda_runtime.h>
#include <cuda_fp16.h>
#include <cuda.h>

// DSSIM — fused separable-Gaussian SSIM + mean.
// Round 10: proven-best combination — round-8 main (early TMA issue,
// standalone) + round-7 two-stage reduction tail.

#define IMH 512
#define IMW 512
#define TW 32
#define TH 64
#define SROWS 74            // TH + 10
#define STP 48              // TMA tile pitch in floats (192B rows)
#define INP 50              // fallback sIn pitch in float2 units
#define HP 33               // sH pitch in 8B units
#define GX 16
#define GY 8
#define NBLK (GX*GY*96)     // 12288
#define NRED1 48            // 48*256 = 12288
#define C1F 1.0e-4f
#define C2F 9.0e-4f
#define TMA_BYTES (2 * SROWS * STP * 4)   // 28416

typedef unsigned long long u64;

static __device__ __forceinline__ u64 pk2(float lo, float hi) {
    u64 r; asm("mov.b64 %0, {%1,%2};" : "=l"(r) : "f"(lo), "f"(hi)); return r;
}
static __device__ __forceinline__ void up2(u64 v, float& lo, float& hi) {
    asm("mov.b64 {%0,%1}, %2;" : "=f"(lo), "=f"(hi) : "l"(v));
}
static __device__ __forceinline__ u64 fma2(u64 a, u64 b, u64 c) {
    u64 d; asm("fma.rn.f32x2 %0, %1, %2, %3;" : "=l"(d) : "l"(a), "l"(b), "l"(c)); return d;
}
static __device__ __forceinline__ u64 add2(u64 a, u64 b) {
    u64 d; asm("add.rn.f32x2 %0, %1, %2;" : "=l"(d) : "l"(a), "l"(b)); return d;
}
static __device__ __forceinline__ unsigned smem32(const void* p) {
    unsigned a; asm("{ .reg .u64 t; cvta.to.shared.u64 t, %1; cvt.u32.u64 %0, t; }" : "=r"(a) : "l"(p));
    return a;
}

struct __align__(8) H2x2 { __half2 a, b; };   // (mu1', mu2'), (S', xy')

__device__ float  g_part[NBLK];
__device__ double g_part2[NRED1];

// Accumulate shifted pixel pair (a', b') at tap kk into 8 streamed outputs.
#define ACCS(kk, va, vb) do {                                           \
    const float _s  = fmaf((va), (va), (vb) * (vb));                    \
    const float _xy = (va) * (vb);                                      \
    const u64 _A = pk2((va), (vb));                                     \
    const u64 _B = pk2(_s, _xy);                                        \
    _Pragma("unroll")                                                   \
    for (int j = 0; j < 8; ++j) {                                       \
        const int t = (kk) - j;                                         \
        if (t >= 0 && t <= 10) {                                        \
            const int wi = (t < 6) ? t : 10 - t;                        \
            aA[j] = fma2(ww[wi], _A, aA[j]);                            \
            aB[j] = fma2(ww[wi], _B, aB[j]);                            \
        }                                                               \
    }                                                                   \
} while (0)

// V-pass + SSIM epilogue + block partial (shared by both kernels).
#define V_PASS_AND_REDUCE()                                                  \
    __half2 wh[6];                                                           \
    _Pragma("unroll")                                                        \
    for (int i = 0; i < 6; ++i) wh[i] = __float2half2_rn(sW[i]);             \
    const int x  = tid & 31;                                                 \
    const int ys = (tid >> 5) << 3;                                          \
    __half2 vA[8], vB[8];                                                    \
    const __half2 hz = __float2half2_rn(0.f);                                \
    _Pragma("unroll")                                                        \
    for (int j = 0; j < 8; ++j) { vA[j] = hz; vB[j] = hz; }                  \
    _Pragma("unroll")                                                        \
    for (int k = 0; k < 18; ++k) {                                           \
        const H2x2 h = sH[(ys + k) * HP + x];                                \
        _Pragma("unroll")                                                    \
        for (int j = 0; j < 8; ++j) {                                        \
            const int t = k - j;                                             \
            if (t >= 0 && t <= 10) {                                         \
                const int wi = (t < 6) ? t : 10 - t;                         \
                vA[j] = __hfma2(wh[wi], h.a, vA[j]);                         \
                vB[j] = __hfma2(wh[wi], h.b, vB[j]);                         \
            }                                                                \
        }                                                                    \
    }                                                                        \
    float local = 0.f;                                                       \
    _Pragma("unroll")                                                        \
    for (int j = 0; j < 8; ++j) {                                            \
        const float2 m  = __half22float2(vA[j]);  /* mu1', mu2' */           \
        const float2 sx = __half22float2(vB[j]);  /* S', bxy' */             \
        const float t2 = m.x + m.y;                                          \
        const float p  = m.x * m.y;                                          \
        const float q2 = fmaf(m.x, m.x, m.y * m.y);                          \
        const float mu12 = fmaf(0.5f, t2, p + 0.25f);                        \
        const float A2   = q2 + t2 + 0.5f;                                   \
        const float s12  = sx.y - p;                                         \
        const float sS   = sx.x - q2;                                        \
        const float num = fmaf(2.f, mu12, C1F) * fmaf(2.f, s12, C2F);        \
        const float den = (A2 + C1F) * (sS + C2F);                           \
        local += (1.f - __fdividef(num, den)) * 0.5f;                        \
    }                                                                        \
    _Pragma("unroll")                                                        \
    for (int o = 16; o; o >>= 1) local += __shfl_xor_sync(0xffffffffu, local, o); \
    if ((tid & 31) == 0) sWarp[tid >> 5] = local;                            \
    __syncthreads();                                                         \
    if (tid == 0) {                                                          \
        float bs = 0.f;                                                      \
        _Pragma("unroll")                                                    \
        for (int i = 0; i < 8; ++i) bs += sWarp[i];                          \
        g_part[((int)blockIdx.z * GY + (int)blockIdx.y) * GX + (int)blockIdx.x] = bs; \
    }

// ---------------------------------------------------------------------------
// TMA path
// ---------------------------------------------------------------------------
__global__ __launch_bounds__(256, 4) void dssim_tma(
    const __grid_constant__ CUtensorMap tm1,
    const __grid_constant__ CUtensorMap tm2,
    const float* __restrict__ kern)
{
    __shared__ alignas(128) float sT1[SROWS * STP];
    __shared__ alignas(128) float sT2[SROWS * STP];
    __shared__ alignas(16)  H2x2  sH[SROWS * HP];
    __shared__ alignas(8)   u64   mbar;
    __shared__ float sW[6];
    __shared__ float sWarp[8];

    const int tid = threadIdx.x;
    const int x0 = blockIdx.x * TW;
    const int y0 = blockIdx.y * TH;

    // tid0: init barrier, fence, and launch both TMA loads immediately.
    if (tid == 0) {
        const unsigned mb = smem32(&mbar);
        asm volatile("mbarrier.init.shared.b64 [%0], 1;" :: "r"(mb) : "memory");
        asm volatile("fence.proxy.async.shared::cta;" ::: "memory");
        asm volatile("mbarrier.arrive.expect_tx.shared.b64 _, [%0], %1;"
                     :: "r"(mb), "r"((unsigned)TMA_BYTES) : "memory");
        const int cx = x0 - 8, cy = y0 - 5, cz = blockIdx.z;
        asm volatile("cp.async.bulk.tensor.3d.shared::cta.global.tile.mbarrier::complete_tx::bytes "
                     "[%0], [%1, {%2, %3, %4}], [%5];"
                     :: "r"(smem32(sT1)), "l"(&tm1), "r"(cx), "r"(cy), "r"(cz), "r"(mb) : "memory");
        asm volatile("cp.async.bulk.tensor.3d.shared::cta.global.tile.mbarrier::complete_tx::bytes "
                     "[%0], [%1, {%2, %3, %4}], [%5];"
                     :: "r"(smem32(sT2)), "l"(&tm2), "r"(cx), "r"(cy), "r"(cz), "r"(mb) : "memory");
    }
    // Weight prep overlaps the TMA flight.
    if (tid < 6) {
        float s = 0.f;
        #pragma unroll
        for (int j = 0; j < 11; ++j) s += kern[tid * 11 + j];
        sW[tid] = s;
    }
    __syncthreads();   // orders mbarrier.init before other threads' try_wait

    u64 ww[6];
    #pragma unroll
    for (int i = 0; i < 6; ++i) { float w = sW[i]; ww[i] = pk2(w, w); }
    const u64 NEGH = pk2(-0.5f, -0.5f);

    // wait for TMA (acquire)
    {
        const unsigned mb = smem32(&mbar);
        unsigned done;
        asm volatile("{\n\t.reg .pred p;\n\t"
                     "mbarrier.try_wait.parity.acquire.cta.shared::cta.b64 p, [%1], 0;\n\t"
                     "selp.b32 %0, 1, 0, p;\n\t}"
                     : "=r"(done) : "r"(mb) : "memory");
        if (!done) {
            asm volatile("{\n\t.reg .pred P1;\n\t"
                         "W0_%=:\n\t"
                         "mbarrier.try_wait.parity.acquire.cta.shared::cta.b64 P1, [%0], 0, 0x989680;\n\t"
                         "@P1 bra.uni W1_%=;\n\t"
                         "bra.uni W0_%=;\n\t"
                         "W1_%=:\n\t}" :: "r"(mb) : "memory");
        }
    }

    // ---- H-pass: 296 tasks (74 rows x 4 groups-of-8), LDS.128 from both tiles ----
    for (int g = tid; g < SROWS * 4; g += 256) {
        const int r  = g >> 2;
        const int cx = (g & 3) << 3;
        u64 aA[8], aB[8];
        #pragma unroll
        for (int j = 0; j < 8; ++j) { aA[j] = 0ull; aB[j] = 0ull; }

        const float4* r1 = (const float4*)&sT1[r * STP];
        const float4* r2 = (const float4*)&sT2[r * STP];
        const int qb = cx >> 2;
        #pragma unroll
        for (int qi = 0; qi < 6; ++qi) {
            const float4 A4 = r1[qb + qi];
            const float4 B4 = r2[qb + qi];
            u64 pa, pb; float a0,a1,b0,b1,a2,a3,b2,b3;
            pa = add2(pk2(A4.x, A4.y), NEGH); up2(pa, a0, a1);
            pb = add2(pk2(B4.x, B4.y), NEGH); up2(pb, b0, b1);
            {
                const int k = 4 * qi - 3;
                if (k >= 0 && k <= 17) ACCS(k, a0, b0);
                if (k + 1 >= 0 && k + 1 <= 17) ACCS(k + 1, a1, b1);
            }
            pa = add2(pk2(A4.z, A4.w), NEGH); up2(pa, a2, a3);
            pb = add2(pk2(B4.z, B4.w), NEGH); up2(pb, b2, b3);
            {
                const int k = 4 * qi - 1;
                if (k >= 0 && k <= 17) ACCS(k, a2, b2);
                if (k + 1 <= 17) ACCS(k + 1, a3, b3);
            }
        }

        #pragma unroll
        for (int j = 0; j < 8; ++j) {
            float m1, m2, s, xy;
            up2(aA[j], m1, m2);
            up2(aB[j], s, xy);
            H2x2 h;
            h.a = __floats2half2_rn(m1, m2);
            h.b = __floats2half2_rn(s, xy);
            sH[r * HP + cx + j] = h;
        }
    }
    __syncthreads();

    V_PASS_AND_REDUCE()
}

// ---------------------------------------------------------------------------
// Fallback path (LDG staging), same math
// ---------------------------------------------------------------------------
__global__ __launch_bounds__(256, 4) void dssim_ldg(
    const float* __restrict__ im1,
    const float* __restrict__ im2,
    const float* __restrict__ kern)
{
    __shared__ float2 sIn[SROWS * INP];
    __shared__ H2x2   sH[SROWS * HP];
    __shared__ float  sW[6];
    __shared__ float  sWarp[8];

    const int tid = threadIdx.x;
    const int x0 = blockIdx.x * TW;
    const int y0 = blockIdx.y * TH;
    const size_t pbase = (size_t)blockIdx.z * (IMH * IMW);

    if (tid < 6) {
        float s = 0.f;
        #pragma unroll
        for (int j = 0; j < 11; ++j) s += kern[tid * 11 + j];
        sW[tid] = s;
    }

    for (int i = tid; i < SROWS * 12; i += 256) {
        const int r = i / 12;
        const int q = i - r * 12;
        const int gy = y0 + r - 5;
        const int gx = x0 + (q << 2) - 8;
        float4 a = make_float4(0.f, 0.f, 0.f, 0.f);
        float4 b = a;
        if ((unsigned)gy < IMH && gx >= 0 && gx <= IMW - 4) {
            const size_t o = pbase + (size_t)gy * IMW + gx;
            a = *(const float4*)(im1 + o);
            b = *(const float4*)(im2 + o);
        }
        float4* dst = (float4*)&sIn[r * INP + (q << 2)];
        dst[0] = make_float4(a.x - 0.5f, b.x - 0.5f, a.y - 0.5f, b.y - 0.5f);
        dst[1] = make_float4(a.z - 0.5f, b.z - 0.5f, a.w - 0.5f, b.w - 0.5f);
    }
    __syncthreads();

    u64 ww[6];
    #pragma unroll
    for (int i = 0; i < 6; ++i) { float w = sW[i]; ww[i] = pk2(w, w); }

    for (int g = tid; g < SROWS * 4; g += 256) {
        const int r  = g >> 2;
        const int cx = (g & 3) << 3;
        u64 aA[8], aB[8];
        #pragma unroll
        for (int j = 0; j < 8; ++j) { aA[j] = 0ull; aB[j] = 0ull; }

        const float4* rp4 = (const float4*)&sIn[r * INP];
        const int qb = (cx >> 1) + 1;
        #pragma unroll
        for (int q = 0; q < 10; ++q) {
            const float4 L = rp4[qb + q];
            if (q > 0) ACCS(2 * q - 1, L.x, L.y);
            if (q < 9) ACCS(2 * q,     L.z, L.w);
        }

        #pragma unroll
        for (int j = 0; j < 8; ++j) {
            float m1, m2, s, xy;
            up2(aA[j], m1, m2);
            up2(aB[j], s, xy);
            H2x2 h;
            h.a = __floats2half2_rn(m1, m2);
            h.b = __floats2half2_rn(s, xy);
            sH[r * HP + cx + j] = h;
        }
    }
    __syncthreads();

    V_PASS_AND_REDUCE()
}

// ---------------------------------------------------------------------------
// Two-stage deterministic reduction (round-7 proven tail, 5.8 us)
// ---------------------------------------------------------------------------
__global__ __launch_bounds__(256) void dssim_reduce1()
{
    __shared__ double sd[256];
    const int t = threadIdx.x;
    sd[t] = (double)g_part[blockIdx.x * 256 + t];
    __syncthreads();
    #pragma unroll
    for (int o = 128; o; o >>= 1) {
        if (t < o) sd[t] += sd[t + o];
        __syncthreads();
    }
    if (t == 0) g_part2[blockIdx.x] = sd[0];
}

__global__ __launch_bounds__(64) void dssim_reduce2(float* __restrict__ out)
{
    __shared__ double sd[64];
    const int t = threadIdx.x;
    sd[t] = (t < NRED1) ? g_part2[t] : 0.0;
    __syncthreads();
    #pragma unroll
    for (int o = 32; o; o >>= 1) {
        if (t < o) sd[t] += sd[t + o];
        __syncthreads();
    }
    if (t == 0) out[0] = (float)(sd[0] / (double)(32.0 * 3.0 * 512.0 * 512.0));
}

// ---------------------------------------------------------------------------
// Host
// ---------------------------------------------------------------------------
typedef CUresult (*PFN_tmap_encode)(
    CUtensorMap*, CUtensorMapDataType, cuuint32_t, void*,
    const cuuint64_t*, const cuuint64_t*, const cuuint32_t*, const cuuint32_t*,
    CUtensorMapInterleave, CUtensorMapSwizzle, CUtensorMapL2promotion,
    CUtensorMapFloatOOBfill);

static bool build_tmap(PFN_tmap_encode enc, CUtensorMap* tm, const void* ptr)
{
    cuuint64_t dims[3]    = {IMW, IMH, 96};
    cuuint64_t strides[2] = {IMW * 4ull, (cuuint64_t)IMH * IMW * 4ull};
    cuuint32_t box[3]     = {STP, SROWS, 1};
    cuuint32_t es[3]      = {1, 1, 1};
    return enc(tm, CU_TENSOR_MAP_DATA_TYPE_FLOAT32, 3, (void*)ptr,
               dims, strides, box, es,
               CU_TENSOR_MAP_INTERLEAVE_NONE, CU_TENSOR_MAP_SWIZZLE_NONE,
               CU_TENSOR_MAP_L2_PROMOTION_L2_128B,
               CU_TENSOR_MAP_FLOAT_OOB_FILL_NONE) == CUDA_SUCCESS;
}

extern "C" void kernel_launch(void* const* d_in, const int* in_sizes, int n_in,
                              void* d_out, int out_size)
{
    const float* im1  = (const float*)d_in[0];
    const float* im2  = (const float*)d_in[1];
    const float* kern = (const float*)d_in[2];
    float* out = (float*)d_out;

    dim3 grid(GX, GY, 96);

    PFN_tmap_encode enc = nullptr;
    {
        void* fp = nullptr;
        cudaDriverEntryPointQueryResult st = cudaDriverEntryPointSymbolNotFound;
        if (cudaGetDriverEntryPoint("cuTensorMapEncodeTiled", &fp,
                                    cudaEnableDefault, &st) == cudaSuccess &&
            st == cudaDriverEntryPointSuccess)
            enc = (PFN_tmap_encode)fp;
    }

    CUtensorMap tm1, tm2;
    bool tma_ok = enc && build_tmap(enc, &tm1, im1) && build_tmap(enc, &tm2, im2);

    if (tma_ok)
        dssim_tma<<<grid, 256>>>(tm1, tm2, kern);
    else
        dssim_ldg<<<grid, 256>>>(im1, im2, kern);

    dssim_reduce1<<<NRED1, 256>>>();
    dssim_reduce2<<<1, 64>>>(out);
}